// round 4
// baseline (speedup 1.0000x reference)
#include <cuda_runtime.h>
#include <math.h>

#define BB  8
#define NPT 2048
#define NTOT (BB*NPT)
#define HID 256
#define NITER 14

// ---------------- persistent scratch (device globals; no allocation) ----------------
__device__ float4 g_xp[NTOT];   // noise points packed: (x,y,z,|x|^2)
__device__ float4 g_yp[NTOT];   // x0 points packed:    (x,y,z,|y|^2)
__device__ float  g_f[NTOT];
__device__ float  g_g[NTOT];
__device__ float  g_std[BB];
__device__ int    g_idx[NTOT];

// ---------------- per-batch std (ddof=1), two-pass like jnp.std ----------------
__global__ void k_std(const float* __restrict__ cloud) {
    __shared__ float red[256];
    const int b = blockIdx.x;
    const float* p = cloud + b * NPT * 3;
    const int tid = threadIdx.x;
    float s = 0.f;
    for (int i = tid; i < NPT * 3; i += 256) s += p[i];
    red[tid] = s; __syncthreads();
    for (int o = 128; o > 0; o >>= 1) { if (tid < o) red[tid] += red[tid + o]; __syncthreads(); }
    const float mean = red[0] / (float)(NPT * 3);
    __syncthreads();
    float s2 = 0.f;
    for (int i = tid; i < NPT * 3; i += 256) { float d = p[i] - mean; s2 = fmaf(d, d, s2); }
    red[tid] = s2; __syncthreads();
    for (int o = 128; o > 0; o >>= 1) { if (tid < o) red[tid] += red[tid + o]; __syncthreads(); }
    if (tid == 0) g_std[b] = sqrtf(red[0] / (float)(NPT * 3 - 1));
}

// ---------------- pack points + norms, zero potentials ----------------
__global__ void k_pack(const float* __restrict__ cloud, const float* __restrict__ noise) {
    int i = blockIdx.x * blockDim.x + threadIdx.x;
    if (i >= NTOT) return;
    int b = i >> 11;
    float sd = g_std[b];
    float c0 = cloud[i * 3 + 0] / sd;
    float c1 = cloud[i * 3 + 1] / sd;
    float c2 = cloud[i * 3 + 2] / sd;
    // |y|^2 like jnp.sum(y*y,-1): ((y0*y0)+(y1*y1))+(y2*y2), no fma contraction
    float yn = __fadd_rn(__fadd_rn(__fmul_rn(c0, c0), __fmul_rn(c1, c1)), __fmul_rn(c2, c2));
    g_yp[i] = make_float4(c0, c1, c2, yn);
    float n0 = noise[i * 3 + 0], n1 = noise[i * 3 + 1], n2 = noise[i * 3 + 2];
    float xn = __fadd_rn(__fadd_rn(__fmul_rn(n0, n0), __fmul_rn(n1, n1)), __fmul_rn(n2, n2));
    g_xp[i] = make_float4(n0, n1, n2, xn);
    g_f[i] = 0.f;
    g_g[i] = 0.f;
}

// -log(2048) as fp32 (uniform constant shifts cancel through the softmin anyway)
#define LOGC (-7.6246189861593985f)

// ---------------- one Sinkhorn half-update ----------------
// psi[q] = -eps * LSE_p( logc + (phi_p - 0.5*max(|q|^2+|p|^2-2 q.p, 0)) / eps )
// DIR==0: q = noise(x), p = x0(y), phi = g  -> writes f
// DIR==1: q = x0(y),   p = noise(x), phi = f -> writes g
template <int DIR>
__global__ void __launch_bounds__(256) k_half(float eps, float inv_eps) {
    __shared__ float4 sp[NPT];
    __shared__ float  sph[NPT];
    const int b = blockIdx.y;
    const int base = b * NPT;
    const float4* __restrict__ Pp  = DIR ? g_xp : g_yp;
    const float4* __restrict__ Pq  = DIR ? g_yp : g_xp;
    const float*  __restrict__ phi = DIR ? g_f  : g_g;
    float* __restrict__ outp       = DIR ? g_g  : g_f;

    const int tid = threadIdx.x;
    for (int j = tid; j < NPT; j += 256) {
        sp[j]  = Pp[base + j];
        sph[j] = phi[base + j];
    }
    __syncthreads();

    const int warp = tid >> 5, lane = tid & 31;
    const int r0 = blockIdx.x * 32 + warp * 4;

    float qx[4], qy[4], qz[4], qn[4];
#pragma unroll
    for (int k = 0; k < 4; k++) {
        float4 q = Pq[base + r0 + k];
        qx[k] = q.x; qy[k] = q.y; qz[k] = q.z; qn[k] = q.w;
    }

    // pass 1: row maxima
    float m0 = -INFINITY, m1 = -INFINITY, m2 = -INFINITY, m3 = -INFINITY;
#pragma unroll 4
    for (int j = lane; j < NPT; j += 32) {
        const float4 p = sp[j];
        const float ph = sph[j];
        {
            float d = fmaf(qz[0], p.z, fmaf(qy[0], p.y, __fmul_rn(qx[0], p.x)));
            float s = fmaf(-2.f, d, __fadd_rn(qn[0], p.w));
            s = fmaxf(s, 0.f);
            float a = fmaf(__fmul_rn(fmaf(-0.5f, s, ph), inv_eps), 1.f, 0.f);
            a = __fadd_rn(LOGC, __fmul_rn(fmaf(-0.5f, s, ph), inv_eps));
            m0 = fmaxf(m0, a);
        }
        {
            float d = fmaf(qz[1], p.z, fmaf(qy[1], p.y, __fmul_rn(qx[1], p.x)));
            float s = fmaf(-2.f, d, __fadd_rn(qn[1], p.w));
            s = fmaxf(s, 0.f);
            float a = __fadd_rn(LOGC, __fmul_rn(fmaf(-0.5f, s, ph), inv_eps));
            m1 = fmaxf(m1, a);
        }
        {
            float d = fmaf(qz[2], p.z, fmaf(qy[2], p.y, __fmul_rn(qx[2], p.x)));
            float s = fmaf(-2.f, d, __fadd_rn(qn[2], p.w));
            s = fmaxf(s, 0.f);
            float a = __fadd_rn(LOGC, __fmul_rn(fmaf(-0.5f, s, ph), inv_eps));
            m2 = fmaxf(m2, a);
        }
        {
            float d = fmaf(qz[3], p.z, fmaf(qy[3], p.y, __fmul_rn(qx[3], p.x)));
            float s = fmaf(-2.f, d, __fadd_rn(qn[3], p.w));
            s = fmaxf(s, 0.f);
            float a = __fadd_rn(LOGC, __fmul_rn(fmaf(-0.5f, s, ph), inv_eps));
            m3 = fmaxf(m3, a);
        }
    }
#pragma unroll
    for (int o = 16; o; o >>= 1) {
        m0 = fmaxf(m0, __shfl_xor_sync(0xffffffffu, m0, o));
        m1 = fmaxf(m1, __shfl_xor_sync(0xffffffffu, m1, o));
        m2 = fmaxf(m2, __shfl_xor_sync(0xffffffffu, m2, o));
        m3 = fmaxf(m3, __shfl_xor_sync(0xffffffffu, m3, o));
    }

    // pass 2: sum of exp(a - m)
    float s0 = 0.f, s1 = 0.f, s2 = 0.f, s3 = 0.f;
#pragma unroll 4
    for (int j = lane; j < NPT; j += 32) {
        const float4 p = sp[j];
        const float ph = sph[j];
        {
            float d = fmaf(qz[0], p.z, fmaf(qy[0], p.y, __fmul_rn(qx[0], p.x)));
            float s = fmaf(-2.f, d, __fadd_rn(qn[0], p.w));
            s = fmaxf(s, 0.f);
            float a = __fadd_rn(LOGC, __fmul_rn(fmaf(-0.5f, s, ph), inv_eps));
            s0 += __expf(a - m0);
        }
        {
            float d = fmaf(qz[1], p.z, fmaf(qy[1], p.y, __fmul_rn(qx[1], p.x)));
            float s = fmaf(-2.f, d, __fadd_rn(qn[1], p.w));
            s = fmaxf(s, 0.f);
            float a = __fadd_rn(LOGC, __fmul_rn(fmaf(-0.5f, s, ph), inv_eps));
            s1 += __expf(a - m1);
        }
        {
            float d = fmaf(qz[2], p.z, fmaf(qy[2], p.y, __fmul_rn(qx[2], p.x)));
            float s = fmaf(-2.f, d, __fadd_rn(qn[2], p.w));
            s = fmaxf(s, 0.f);
            float a = __fadd_rn(LOGC, __fmul_rn(fmaf(-0.5f, s, ph), inv_eps));
            s2 += __expf(a - m2);
        }
        {
            float d = fmaf(qz[3], p.z, fmaf(qy[3], p.y, __fmul_rn(qx[3], p.x)));
            float s = fmaf(-2.f, d, __fadd_rn(qn[3], p.w));
            s = fmaxf(s, 0.f);
            float a = __fadd_rn(LOGC, __fmul_rn(fmaf(-0.5f, s, ph), inv_eps));
            s3 += __expf(a - m3);
        }
    }
#pragma unroll
    for (int o = 16; o; o >>= 1) {
        s0 += __shfl_xor_sync(0xffffffffu, s0, o);
        s1 += __shfl_xor_sync(0xffffffffu, s1, o);
        s2 += __shfl_xor_sync(0xffffffffu, s2, o);
        s3 += __shfl_xor_sync(0xffffffffu, s3, o);
    }

    if (lane == 0) {
        outp[base + r0 + 0] = __fmul_rn(-eps, __fadd_rn(logf(s0), m0));
        outp[base + r0 + 1] = __fmul_rn(-eps, __fadd_rn(logf(s1), m1));
        outp[base + r0 + 2] = __fmul_rn(-eps, __fadd_rn(logf(s2), m2));
        outp[base + r0 + 3] = __fmul_rn(-eps, __fadd_rn(logf(s3), m3));
    }
}

// ---------------- argmin over m of (sqdist(x_n, y_m) - g_m), first-index ties ----------------
__global__ void __launch_bounds__(256) k_argmin() {
    __shared__ float4 sp[NPT];
    __shared__ float  sg[NPT];
    const int b = blockIdx.y;
    const int base = b * NPT;
    const int tid = threadIdx.x;
    for (int j = tid; j < NPT; j += 256) { sp[j] = g_yp[base + j]; sg[j] = g_g[base + j]; }
    __syncthreads();
    const int warp = tid >> 5, lane = tid & 31;
    const int r0 = blockIdx.x * 32 + warp * 4;

    float qx[4], qy[4], qz[4], qn[4];
#pragma unroll
    for (int k = 0; k < 4; k++) {
        float4 q = g_xp[base + r0 + k];
        qx[k] = q.x; qy[k] = q.y; qz[k] = q.z; qn[k] = q.w;
    }
    float bv[4] = {INFINITY, INFINITY, INFINITY, INFINITY};
    int   bi[4] = {0, 0, 0, 0};
#pragma unroll 2
    for (int j = lane; j < NPT; j += 32) {
        const float4 p = sp[j];
        const float gg = sg[j];
#pragma unroll
        for (int k = 0; k < 4; k++) {
            float d = fmaf(qz[k], p.z, fmaf(qy[k], p.y, __fmul_rn(qx[k], p.x)));
            float s = fmaf(-2.f, d, __fadd_rn(qn[k], p.w));
            s = fmaxf(s, 0.f);
            float v = __fadd_rn(s, -gg);
            if (v < bv[k]) { bv[k] = v; bi[k] = j; }
        }
    }
#pragma unroll
    for (int k = 0; k < 4; k++) {
#pragma unroll
        for (int o = 16; o; o >>= 1) {
            float v2 = __shfl_xor_sync(0xffffffffu, bv[k], o);
            int   i2 = __shfl_xor_sync(0xffffffffu, bi[k], o);
            if (v2 < bv[k] || (v2 == bv[k] && i2 < bi[k])) { bv[k] = v2; bi[k] = i2; }
        }
    }
    if (lane == 0) {
        g_idx[base + r0 + 0] = bi[0];
        g_idx[base + r0 + 1] = bi[1];
        g_idx[base + r0 + 2] = bi[2];
        g_idx[base + r0 + 3] = bi[3];
    }
}

// ---------------- gather + flow-matching MLP head, write (v_pred, v) ----------------
__global__ void __launch_bounds__(256) k_mlp(const float* __restrict__ noise, const float* __restrict__ tt,
                                             const float* __restrict__ W1, const float* __restrict__ Wt,
                                             const float* __restrict__ b1, const float* __restrict__ W2,
                                             const float* __restrict__ b2, float* __restrict__ out) {
    __shared__ float sW1[3 * HID], sW2[HID * 3], sWt[HID], sb1[HID];
    const int tid = threadIdx.x;
    for (int i = tid; i < 3 * HID; i += 256) { sW1[i] = W1[i]; sW2[i] = W2[i]; }
    for (int i = tid; i < HID; i += 256) { sWt[i] = Wt[i]; sb1[i] = b1[i]; }
    __syncthreads();

    const int p = blockIdx.x * 256 + tid;
    const int b = p >> 11;
    const float t = tt[b];
    const int id = g_idx[p];
    const float4 y = g_yp[(b << 11) + id];
    const float n0 = noise[p * 3 + 0], n1 = noise[p * 3 + 1], n2 = noise[p * 3 + 2];
    const float v0 = __fadd_rn(n0, -y.x);
    const float v1 = __fadd_rn(n1, -y.y);
    const float v2 = __fadd_rn(n2, -y.z);
    const float omt = __fadd_rn(1.f, -t);
    const float x0t = __fadd_rn(__fmul_rn(omt, y.x), __fmul_rn(t, n0));
    const float x1t = __fadd_rn(__fmul_rn(omt, y.y), __fmul_rn(t, n1));
    const float x2t = __fadd_rn(__fmul_rn(omt, y.z), __fmul_rn(t, n2));

    float a0 = b2[0], a1 = b2[1], a2 = b2[2];
#pragma unroll 8
    for (int j = 0; j < HID; j++) {
        float h = fmaf(x2t, sW1[2 * HID + j], fmaf(x1t, sW1[HID + j], __fmul_rn(x0t, sW1[j])));
        h = __fadd_rn(__fadd_rn(h, __fmul_rn(t, sWt[j])), sb1[j]);
        h = fmaxf(h, 0.f);
        a0 = fmaf(h, sW2[j * 3 + 0], a0);
        a1 = fmaf(h, sW2[j * 3 + 1], a1);
        a2 = fmaf(h, sW2[j * 3 + 2], a2);
    }
    out[p * 3 + 0] = a0;
    out[p * 3 + 1] = a1;
    out[p * 3 + 2] = a2;
    out[NTOT * 3 + p * 3 + 0] = v0;
    out[NTOT * 3 + p * 3 + 1] = v1;
    out[NTOT * 3 + p * 3 + 2] = v2;
}

// ---------------- launcher ----------------
extern "C" void kernel_launch(void* const* d_in, const int* in_sizes, int n_in,
                              void* d_out, int out_size) {
    const float* cloud = (const float*)d_in[0];
    const float* noise = (const float*)d_in[1];
    const float* t     = (const float*)d_in[2];
    const float* W1    = (const float*)d_in[3];
    const float* Wt    = (const float*)d_in[4];
    const float* b1    = (const float*)d_in[5];
    const float* W2    = (const float*)d_in[6];
    const float* b2    = (const float*)d_in[7];
    float* out = (float*)d_out;

    k_std<<<BB, 256>>>(cloud);
    k_pack<<<NTOT / 256, 256>>>(cloud, noise);

    // EPS_LIST = np.geomspace(32.0, 0.001**2, 14).astype(np.float32)
    const double blur2 = 0.001 * 0.001;
    const double l0 = log10(32.0);
    const double l1 = log10(blur2);
    const double step = (l1 - l0) / (double)(NITER - 1);
    const dim3 grid(NPT / 32, BB);

    for (int it = 0; it < NITER; it++) {
        double ev;
        if (it == 0)              ev = 32.0;
        else if (it == NITER - 1) ev = blur2;
        else                      ev = pow(10.0, l0 + (double)it * step);
        const float eps = (float)ev;
        const float inv_eps = 1.0f / eps;
        k_half<0><<<grid, 256>>>(eps, inv_eps);  // f-update (reduce over y with g)
        k_half<1><<<grid, 256>>>(eps, inv_eps);  // g-update (reduce over x with f)
    }

    k_argmin<<<grid, 256>>>();
    k_mlp<<<NTOT / 256, 256>>>(noise, t, W1, Wt, b1, W2, b2, out);

    (void)in_sizes; (void)n_in; (void)out_size;
}

// round 5
// speedup vs baseline: 1.1527x; 1.1527x over previous
#include <cuda_runtime.h>
#include <math.h>

#define BB  8
#define NPT 2048
#define NTOT (BB*NPT)
#define HID 256
#define NITER 14

typedef unsigned long long u64;

// ---------------- f32x2 packed helpers (sm_103a) ----------------
__device__ __forceinline__ u64 pk2(float lo, float hi) {
    u64 r; asm("mov.b64 %0,{%1,%2};" : "=l"(r) : "f"(lo), "f"(hi)); return r;
}
__device__ __forceinline__ void up2(u64 v, float& lo, float& hi) {
    asm("mov.b64 {%0,%1},%2;" : "=f"(lo), "=f"(hi) : "l"(v));
}
__device__ __forceinline__ u64 fma2_(u64 a, u64 b, u64 c) {
    u64 r; asm("fma.rn.f32x2 %0,%1,%2,%3;" : "=l"(r) : "l"(a), "l"(b), "l"(c)); return r;
}
__device__ __forceinline__ u64 mul2_(u64 a, u64 b) {
    u64 r; asm("mul.rn.f32x2 %0,%1,%2;" : "=l"(r) : "l"(a), "l"(b)); return r;
}
__device__ __forceinline__ u64 add2_(u64 a, u64 b) {
    u64 r; asm("add.rn.f32x2 %0,%1,%2;" : "=l"(r) : "l"(a), "l"(b)); return r;
}
__device__ __forceinline__ float ex2_(float x) {
    float r; asm("ex2.approx.f32 %0,%1;" : "=f"(r) : "f"(x)); return r;
}

// ---------------- persistent scratch ----------------
__device__ float4 g_xp[NTOT];   // noise points packed: (x,y,z,|x|^2)
__device__ float4 g_yp[NTOT];   // x0 points packed:    (x,y,z,|y|^2)
__device__ float  g_f[NTOT];
__device__ float  g_g[NTOT];
__device__ float  g_std[BB];
__device__ int    g_idx[NTOT];

// ---------------- per-batch std (ddof=1) ----------------
__global__ void k_std(const float* __restrict__ cloud) {
    __shared__ float red[256];
    const int b = blockIdx.x;
    const float* p = cloud + b * NPT * 3;
    const int tid = threadIdx.x;
    float s = 0.f;
    for (int i = tid; i < NPT * 3; i += 256) s += p[i];
    red[tid] = s; __syncthreads();
    for (int o = 128; o > 0; o >>= 1) { if (tid < o) red[tid] += red[tid + o]; __syncthreads(); }
    const float mean = red[0] / (float)(NPT * 3);
    __syncthreads();
    float s2 = 0.f;
    for (int i = tid; i < NPT * 3; i += 256) { float d = p[i] - mean; s2 = fmaf(d, d, s2); }
    red[tid] = s2; __syncthreads();
    for (int o = 128; o > 0; o >>= 1) { if (tid < o) red[tid] += red[tid + o]; __syncthreads(); }
    if (tid == 0) g_std[b] = sqrtf(red[0] / (float)(NPT * 3 - 1));
}

// ---------------- pack points + norms, zero potentials ----------------
__global__ void k_pack(const float* __restrict__ cloud, const float* __restrict__ noise) {
    int i = blockIdx.x * blockDim.x + threadIdx.x;
    if (i >= NTOT) return;
    int b = i >> 11;
    float sd = g_std[b];
    float c0 = cloud[i * 3 + 0] / sd;
    float c1 = cloud[i * 3 + 1] / sd;
    float c2 = cloud[i * 3 + 2] / sd;
    float yn = __fadd_rn(__fadd_rn(__fmul_rn(c0, c0), __fmul_rn(c1, c1)), __fmul_rn(c2, c2));
    g_yp[i] = make_float4(c0, c1, c2, yn);
    float n0 = noise[i * 3 + 0], n1 = noise[i * 3 + 1], n2 = noise[i * 3 + 2];
    float xn = __fadd_rn(__fadd_rn(__fmul_rn(n0, n0), __fmul_rn(n1, n1)), __fmul_rn(n2, n2));
    g_xp[i] = make_float4(n0, n1, n2, xn);
    g_f[i] = 0.f;
    g_g[i] = 0.f;
}

// log2(1/2048) is exactly -11
#define LOGC2 (-11.0f)
#define LN2F  (0.6931471805599453f)

// ---------------- one Sinkhorn half-update (f32x2 packed over the point axis) ----------------
// DIR==0: q = noise(x), p = x0(y), phi = g  -> writes f
// DIR==1: q = x0(y),   p = noise(x), phi = f -> writes g
template <int DIR>
__global__ void __launch_bounds__(256) k_half(float eps, float ie2 /* (1/eps)*log2(e) */) {
    __shared__ float2 sX[NPT/2], sY[NPT/2], sZ[NPT/2], sW[NPT/2], sP[NPT/2];
    const int b = blockIdx.y;
    const int base = b * NPT;
    const float4* __restrict__ Pp  = DIR ? g_xp : g_yp;
    const float4* __restrict__ Pq  = DIR ? g_yp : g_xp;
    const float*  __restrict__ phi = DIR ? g_f  : g_g;
    float* __restrict__ outp       = DIR ? g_g  : g_f;

    const int tid = threadIdx.x;
    // SoA transpose into shared: pair points (2j, 2j+1)
    for (int j = tid; j < NPT / 2; j += 256) {
        float4 a = Pp[base + 2 * j];
        float4 c = Pp[base + 2 * j + 1];
        sX[j] = make_float2(a.x, c.x);
        sY[j] = make_float2(a.y, c.y);
        sZ[j] = make_float2(a.z, c.z);
        sW[j] = make_float2(a.w, c.w);
        sP[j] = ((const float2*)(phi + base))[j];
    }
    __syncthreads();

    const u64* __restrict__ X  = (const u64*)sX;
    const u64* __restrict__ Y  = (const u64*)sY;
    const u64* __restrict__ Z  = (const u64*)sZ;
    const u64* __restrict__ W  = (const u64*)sW;
    const u64* __restrict__ PH = (const u64*)sP;

    const int warp = tid >> 5, lane = tid & 31;
    const int r0 = blockIdx.x * 32 + warp * 4;

    u64 qx2[4], qy2[4], qz2[4], qn2[4];
#pragma unroll
    for (int k = 0; k < 4; k++) {
        float4 q = Pq[base + r0 + k];
        qx2[k] = pk2(q.x, q.x);
        qy2[k] = pk2(q.y, q.y);
        qz2[k] = pk2(q.z, q.z);
        qn2[k] = pk2(q.w, q.w);
    }

    const u64 NEG2 = pk2(-2.0f, -2.0f);
    const u64 NEGQ = pk2(-0.25f, -0.25f);
    const u64 ABSM = 0x7fffffff7fffffffULL;
    const u64 IE2P = pk2(ie2, ie2);

    // ---- pass 1: per-row max of t = fmaf(-0.5, max(s,0), ph), bit-exact via fma(-0.25, s+|s|, ph)
    float ml[4] = {-INFINITY, -INFINITY, -INFINITY, -INFINITY};
    float mh[4] = {-INFINITY, -INFINITY, -INFINITY, -INFINITY};
#pragma unroll 2
    for (int it = 0; it < NPT / 64; ++it) {
        const int jj = lane + it * 32;
        const u64 px = X[jj], py = Y[jj], pz = Z[jj], pw = W[jj], ph = PH[jj];
#pragma unroll
        for (int k = 0; k < 4; k++) {
            u64 d   = fma2_(qz2[k], pz, fma2_(qy2[k], py, mul2_(qx2[k], px)));
            u64 A   = add2_(qn2[k], pw);
            u64 s   = fma2_(NEG2, d, A);
            u64 sps = add2_(s, s & ABSM);            // = 2*max(s,0), exact
            u64 t   = fma2_(NEGQ, sps, ph);          // == fmaf(-0.5, max(s,0), ph) bit-exact
            float tl, th; up2(t, tl, th);
            ml[k] = fmaxf(ml[k], tl);
            mh[k] = fmaxf(mh[k], th);
        }
    }
    float mt[4], m2[4];
    u64 K2[4];
#pragma unroll
    for (int k = 0; k < 4; k++) {
        float m = fmaxf(ml[k], mh[k]);
#pragma unroll
        for (int o = 16; o; o >>= 1) m = fmaxf(m, __shfl_xor_sync(0xffffffffu, m, o));
        mt[k] = m;
        m2[k] = fmaf(m, ie2, LOGC2);                 // max of base-2 exponent args
        float kk = __fadd_rn(LOGC2, -m2[k]);         // fold (-m2) into the affine constant
        K2[k] = pk2(kk, kk);
    }

    // ---- pass 2: sum of exp2(t*ie2 + LOGC2 - m2)
    float acc[4] = {0.f, 0.f, 0.f, 0.f};
#pragma unroll 2
    for (int it = 0; it < NPT / 64; ++it) {
        const int jj = lane + it * 32;
        const u64 px = X[jj], py = Y[jj], pz = Z[jj], pw = W[jj], ph = PH[jj];
#pragma unroll
        for (int k = 0; k < 4; k++) {
            u64 d   = fma2_(qz2[k], pz, fma2_(qy2[k], py, mul2_(qx2[k], px)));
            u64 A   = add2_(qn2[k], pw);
            u64 s   = fma2_(NEG2, d, A);
            u64 sps = add2_(s, s & ABSM);
            u64 t   = fma2_(NEGQ, sps, ph);
            u64 ea  = fma2_(IE2P, t, K2[k]);         // exp2 argument, max-subtracted
            float el, eh; up2(ea, el, eh);
            acc[k] += ex2_(el);
            acc[k] += ex2_(eh);
        }
    }
#pragma unroll
    for (int k = 0; k < 4; k++) {
#pragma unroll
        for (int o = 16; o; o >>= 1) acc[k] += __shfl_xor_sync(0xffffffffu, acc[k], o);
    }

    if (lane == 0) {
#pragma unroll
        for (int k = 0; k < 4; k++) {
            // g = -eps * (ln(sum) + m2*ln2)
            outp[base + r0 + k] = __fmul_rn(-eps, fmaf(m2[k], LN2F, logf(acc[k])));
        }
    }
}

// ---------------- argmin over m of (sqdist - g_m), first-index ties ----------------
__global__ void __launch_bounds__(256) k_argmin() {
    __shared__ float4 sp[NPT];
    __shared__ float  sg[NPT];
    const int b = blockIdx.y;
    const int base = b * NPT;
    const int tid = threadIdx.x;
    for (int j = tid; j < NPT; j += 256) { sp[j] = g_yp[base + j]; sg[j] = g_g[base + j]; }
    __syncthreads();
    const int warp = tid >> 5, lane = tid & 31;
    const int r0 = blockIdx.x * 32 + warp * 4;

    float qx[4], qy[4], qz[4], qn[4];
#pragma unroll
    for (int k = 0; k < 4; k++) {
        float4 q = g_xp[base + r0 + k];
        qx[k] = q.x; qy[k] = q.y; qz[k] = q.z; qn[k] = q.w;
    }
    float bv[4] = {INFINITY, INFINITY, INFINITY, INFINITY};
    int   bi[4] = {0, 0, 0, 0};
#pragma unroll 2
    for (int j = lane; j < NPT; j += 32) {
        const float4 p = sp[j];
        const float gg = sg[j];
#pragma unroll
        for (int k = 0; k < 4; k++) {
            float d = fmaf(qz[k], p.z, fmaf(qy[k], p.y, __fmul_rn(qx[k], p.x)));
            float s = fmaf(-2.f, d, __fadd_rn(qn[k], p.w));
            s = fmaxf(s, 0.f);
            float v = __fadd_rn(s, -gg);
            if (v < bv[k]) { bv[k] = v; bi[k] = j; }
        }
    }
#pragma unroll
    for (int k = 0; k < 4; k++) {
#pragma unroll
        for (int o = 16; o; o >>= 1) {
            float v2 = __shfl_xor_sync(0xffffffffu, bv[k], o);
            int   i2 = __shfl_xor_sync(0xffffffffu, bi[k], o);
            if (v2 < bv[k] || (v2 == bv[k] && i2 < bi[k])) { bv[k] = v2; bi[k] = i2; }
        }
    }
    if (lane == 0) {
#pragma unroll
        for (int k = 0; k < 4; k++) g_idx[base + r0 + k] = bi[k];
    }
}

// ---------------- gather + MLP head, write (v_pred, v) ----------------
__global__ void __launch_bounds__(256) k_mlp(const float* __restrict__ noise, const float* __restrict__ tt,
                                             const float* __restrict__ W1, const float* __restrict__ Wt,
                                             const float* __restrict__ b1, const float* __restrict__ W2,
                                             const float* __restrict__ b2, float* __restrict__ out) {
    __shared__ float sW1[3 * HID], sW2[HID * 3], sWt[HID], sb1[HID];
    const int tid = threadIdx.x;
    for (int i = tid; i < 3 * HID; i += 256) { sW1[i] = W1[i]; sW2[i] = W2[i]; }
    for (int i = tid; i < HID; i += 256) { sWt[i] = Wt[i]; sb1[i] = b1[i]; }
    __syncthreads();

    const int p = blockIdx.x * 256 + tid;
    const int b = p >> 11;
    const float t = tt[b];
    const int id = g_idx[p];
    const float4 y = g_yp[(b << 11) + id];
    const float n0 = noise[p * 3 + 0], n1 = noise[p * 3 + 1], n2 = noise[p * 3 + 2];
    const float v0 = __fadd_rn(n0, -y.x);
    const float v1 = __fadd_rn(n1, -y.y);
    const float v2 = __fadd_rn(n2, -y.z);
    const float omt = __fadd_rn(1.f, -t);
    const float x0t = __fadd_rn(__fmul_rn(omt, y.x), __fmul_rn(t, n0));
    const float x1t = __fadd_rn(__fmul_rn(omt, y.y), __fmul_rn(t, n1));
    const float x2t = __fadd_rn(__fmul_rn(omt, y.z), __fmul_rn(t, n2));

    float a0 = b2[0], a1 = b2[1], a2 = b2[2];
#pragma unroll 8
    for (int j = 0; j < HID; j++) {
        float h = fmaf(x2t, sW1[2 * HID + j], fmaf(x1t, sW1[HID + j], __fmul_rn(x0t, sW1[j])));
        h = __fadd_rn(__fadd_rn(h, __fmul_rn(t, sWt[j])), sb1[j]);
        h = fmaxf(h, 0.f);
        a0 = fmaf(h, sW2[j * 3 + 0], a0);
        a1 = fmaf(h, sW2[j * 3 + 1], a1);
        a2 = fmaf(h, sW2[j * 3 + 2], a2);
    }
    out[p * 3 + 0] = a0;
    out[p * 3 + 1] = a1;
    out[p * 3 + 2] = a2;
    out[NTOT * 3 + p * 3 + 0] = v0;
    out[NTOT * 3 + p * 3 + 1] = v1;
    out[NTOT * 3 + p * 3 + 2] = v2;
}

// ---------------- launcher ----------------
extern "C" void kernel_launch(void* const* d_in, const int* in_sizes, int n_in,
                              void* d_out, int out_size) {
    const float* cloud = (const float*)d_in[0];
    const float* noise = (const float*)d_in[1];
    const float* t     = (const float*)d_in[2];
    const float* W1    = (const float*)d_in[3];
    const float* Wt    = (const float*)d_in[4];
    const float* b1    = (const float*)d_in[5];
    const float* W2    = (const float*)d_in[6];
    const float* b2    = (const float*)d_in[7];
    float* out = (float*)d_out;

    k_std<<<BB, 256>>>(cloud);
    k_pack<<<NTOT / 256, 256>>>(cloud, noise);

    // EPS_LIST = np.geomspace(32.0, 0.001**2, 14).astype(np.float32)
    const double blur2 = 0.001 * 0.001;
    const double l0 = log10(32.0);
    const double l1 = log10(blur2);
    const double step = (l1 - l0) / (double)(NITER - 1);
    const double LOG2E = 1.4426950408889634;
    const dim3 grid(NPT / 32, BB);

    for (int it = 0; it < NITER; it++) {
        double ev;
        if (it == 0)              ev = 32.0;
        else if (it == NITER - 1) ev = blur2;
        else                      ev = pow(10.0, l0 + (double)it * step);
        const float eps = (float)ev;
        const float ie2 = (float)((double)(1.0f / eps) * LOG2E);
        k_half<0><<<grid, 256>>>(eps, ie2);  // f-update
        k_half<1><<<grid, 256>>>(eps, ie2);  // g-update
    }

    k_argmin<<<grid, 256>>>();
    k_mlp<<<NTOT / 256, 256>>>(noise, t, W1, Wt, b1, W2, b2, out);

    (void)in_sizes; (void)n_in; (void)out_size;
}

// round 6
// speedup vs baseline: 1.7921x; 1.5546x over previous
#include <cuda_runtime.h>
#include <math.h>

#define BB  8
#define NPT 2048
#define NTOT (BB*NPT)
#define HID 256
#define NITER 14

typedef unsigned long long u64;

// ---------------- f32x2 packed helpers (sm_103a) ----------------
__device__ __forceinline__ u64 pk2(float lo, float hi) {
    u64 r; asm("mov.b64 %0,{%1,%2};" : "=l"(r) : "f"(lo), "f"(hi)); return r;
}
__device__ __forceinline__ void up2(u64 v, float& lo, float& hi) {
    asm("mov.b64 {%0,%1},%2;" : "=f"(lo), "=f"(hi) : "l"(v));
}
__device__ __forceinline__ u64 fma2_(u64 a, u64 b, u64 c) {
    u64 r; asm("fma.rn.f32x2 %0,%1,%2,%3;" : "=l"(r) : "l"(a), "l"(b), "l"(c)); return r;
}
__device__ __forceinline__ float ex2_(float x) {
    float r; asm("ex2.approx.f32 %0,%1;" : "=f"(r) : "f"(x)); return r;
}

// ---------------- persistent scratch ----------------
__device__ float4 g_xp[NTOT];   // noise points packed: (x,y,z,|x|^2)
__device__ float4 g_yp[NTOT];   // x0 points packed:    (x,y,z,|y|^2)
// deinterleaved coords (SoA) for the reduce-side of k_half
__device__ __align__(16) float g_xx[NTOT], g_xy[NTOT], g_xz[NTOT];
__device__ __align__(16) float g_yx[NTOT], g_yy[NTOT], g_yz[NTOT];
// folded column constants: cX = f - 0.5|x|^2, cY = g - 0.5|y|^2
__device__ __align__(16) float g_cX[NTOT], g_cY[NTOT];
__device__ float  g_g[NTOT];
__device__ float  g_std[BB];
__device__ int    g_idx[NTOT];

// ---------------- per-batch std (ddof=1) ----------------
__global__ void k_std(const float* __restrict__ cloud) {
    __shared__ float red[256];
    const int b = blockIdx.x;
    const float* p = cloud + b * NPT * 3;
    const int tid = threadIdx.x;
    float s = 0.f;
    for (int i = tid; i < NPT * 3; i += 256) s += p[i];
    red[tid] = s; __syncthreads();
    for (int o = 128; o > 0; o >>= 1) { if (tid < o) red[tid] += red[tid + o]; __syncthreads(); }
    const float mean = red[0] / (float)(NPT * 3);
    __syncthreads();
    float s2 = 0.f;
    for (int i = tid; i < NPT * 3; i += 256) { float d = p[i] - mean; s2 = fmaf(d, d, s2); }
    red[tid] = s2; __syncthreads();
    for (int o = 128; o > 0; o >>= 1) { if (tid < o) red[tid] += red[tid + o]; __syncthreads(); }
    if (tid == 0) g_std[b] = sqrtf(red[0] / (float)(NPT * 3 - 1));
}

// ---------------- pack points, deinterleave, init folded constants ----------------
__global__ void k_pack(const float* __restrict__ cloud, const float* __restrict__ noise) {
    int i = blockIdx.x * blockDim.x + threadIdx.x;
    if (i >= NTOT) return;
    int b = i >> 11;
    float sd = g_std[b];
    float c0 = cloud[i * 3 + 0] / sd;
    float c1 = cloud[i * 3 + 1] / sd;
    float c2 = cloud[i * 3 + 2] / sd;
    float yn = __fadd_rn(__fadd_rn(__fmul_rn(c0, c0), __fmul_rn(c1, c1)), __fmul_rn(c2, c2));
    g_yp[i] = make_float4(c0, c1, c2, yn);
    g_yx[i] = c0; g_yy[i] = c1; g_yz[i] = c2;
    float n0 = noise[i * 3 + 0], n1 = noise[i * 3 + 1], n2 = noise[i * 3 + 2];
    float xn = __fadd_rn(__fadd_rn(__fmul_rn(n0, n0), __fmul_rn(n1, n1)), __fmul_rn(n2, n2));
    g_xp[i] = make_float4(n0, n1, n2, xn);
    g_xx[i] = n0; g_xy[i] = n1; g_xz[i] = n2;
    // phi == 0 initially  ->  c = -0.5*|p|^2
    g_cX[i] = __fmul_rn(-0.5f, xn);
    g_cY[i] = __fmul_rn(-0.5f, yn);
}

// log2(1/2048) is exactly -11
#define LOGC2 (-11.0f)
#define LN2F  (0.6931471805599453f)

// ---------------- one Sinkhorn half-update ----------------
// t_raw(i,j) = q_i . p_j + c_j   (c_j = phi_j - 0.5|p_j|^2; row term -0.5|q_i|^2
// is max-invariant and cancels in (t - m): applied only in the epilogue)
// DIR==0: q = noise(x), p = x0(y), c = cY -> writes cX (= f - 0.5|x|^2)
// DIR==1: q = x0(y),   p = noise(x), c = cX -> writes g and cY
template <int DIR>
__global__ void __launch_bounds__(256) k_half(float eps, float ie2 /* (1/eps)*log2(e) */) {
    __shared__ __align__(16) float sX[NPT], sY[NPT], sZ[NPT], sC[NPT];
    const int b = blockIdx.y;
    const int base = b * NPT;
    const float* __restrict__ PXs = DIR ? g_xx : g_yx;
    const float* __restrict__ PYs = DIR ? g_xy : g_yy;
    const float* __restrict__ PZs = DIR ? g_xz : g_yz;
    const float* __restrict__ PCs = DIR ? g_cX : g_cY;
    const float4* __restrict__ Pq = DIR ? g_yp : g_xp;

    const int tid = threadIdx.x;
    {
        const float4* vx = (const float4*)(PXs + base);
        const float4* vy = (const float4*)(PYs + base);
        const float4* vz = (const float4*)(PZs + base);
        const float4* vc = (const float4*)(PCs + base);
        float4* dx = (float4*)sX; float4* dy = (float4*)sY;
        float4* dz = (float4*)sZ; float4* dc = (float4*)sC;
#pragma unroll
        for (int j = tid; j < NPT / 4; j += 256) {
            dx[j] = vx[j]; dy[j] = vy[j]; dz[j] = vz[j]; dc[j] = vc[j];
        }
    }
    __syncthreads();

    const u64* __restrict__ X = (const u64*)sX;
    const u64* __restrict__ Y = (const u64*)sY;
    const u64* __restrict__ Z = (const u64*)sZ;
    const u64* __restrict__ C = (const u64*)sC;

    const int warp = tid >> 5, lane = tid & 31;
    const int r0 = blockIdx.x * 32 + warp * 4;

    u64 qx2[4], qy2[4], qz2[4];
    float qw[4];
#pragma unroll
    for (int k = 0; k < 4; k++) {
        float4 q = Pq[base + r0 + k];
        qx2[k] = pk2(q.x, q.x);
        qy2[k] = pk2(q.y, q.y);
        qz2[k] = pk2(q.z, q.z);
        qw[k] = q.w;
    }

    // ---- pass 1: per-row max of t_raw = q.p + c_j
    float ml[4] = {-INFINITY, -INFINITY, -INFINITY, -INFINITY};
    float mh[4] = {-INFINITY, -INFINITY, -INFINITY, -INFINITY};
#pragma unroll 2
    for (int it = 0; it < NPT / 64; ++it) {
        const int jj = lane + it * 32;
        const u64 px = X[jj], py = Y[jj], pz = Z[jj], pc = C[jj];
#pragma unroll
        for (int k = 0; k < 4; k++) {
            u64 t = fma2_(qz2[k], pz, fma2_(qy2[k], py, fma2_(qx2[k], px, pc)));
            float tl, th; up2(t, tl, th);
            ml[k] = fmaxf(ml[k], tl);
            mh[k] = fmaxf(mh[k], th);
        }
    }
    float mraw[4];
    u64 K2[4];
#pragma unroll
    for (int k = 0; k < 4; k++) {
        float m = fmaxf(ml[k], mh[k]);
#pragma unroll
        for (int o = 16; o; o >>= 1) m = fmaxf(m, __shfl_xor_sync(0xffffffffu, m, o));
        mraw[k] = m;
        float kk = -__fmul_rn(m, ie2);
        K2[k] = pk2(kk, kk);
    }

    const u64 IE2P = pk2(ie2, ie2);

    // ---- pass 2: sum of exp2((t_raw - m_raw)*ie2)
    float aL[4] = {0.f, 0.f, 0.f, 0.f};
    float aH[4] = {0.f, 0.f, 0.f, 0.f};
#pragma unroll 2
    for (int it = 0; it < NPT / 64; ++it) {
        const int jj = lane + it * 32;
        const u64 px = X[jj], py = Y[jj], pz = Z[jj], pc = C[jj];
#pragma unroll
        for (int k = 0; k < 4; k++) {
            u64 t  = fma2_(qz2[k], pz, fma2_(qy2[k], py, fma2_(qx2[k], px, pc)));
            u64 ea = fma2_(IE2P, t, K2[k]);
            float el, eh; up2(ea, el, eh);
            aL[k] += ex2_(el);
            aH[k] += ex2_(eh);
        }
    }
#pragma unroll
    for (int k = 0; k < 4; k++) {
        float a = __fadd_rn(aL[k], aH[k]);
#pragma unroll
        for (int o = 16; o; o >>= 1) a += __shfl_xor_sync(0xffffffffu, a, o);
        aL[k] = a;
    }

    if (lane == 0) {
#pragma unroll
        for (int k = 0; k < 4; k++) {
            // m_full = m_raw - 0.5|q|^2 ; m2 = m_full*ie2 + LOGC2
            float mfull = fmaf(-0.5f, qw[k], mraw[k]);
            float m2 = fmaf(mfull, ie2, LOGC2);
            float res = __fmul_rn(-eps, fmaf(m2, LN2F, logf(aL[k])));
            const int i = base + r0 + k;
            if (DIR == 0) {
                g_cX[i] = fmaf(-0.5f, qw[k], res);     // f - 0.5|x|^2 for next half
            } else {
                g_g[i]  = res;                          // needed by argmin
                g_cY[i] = fmaf(-0.5f, qw[k], res);     // g - 0.5|y|^2 for next iter
            }
        }
    }
}

// ---------------- argmin over m of (sqdist - g_m), first-index ties ----------------
__global__ void __launch_bounds__(256) k_argmin() {
    __shared__ float4 sp[NPT];
    __shared__ float  sg[NPT];
    const int b = blockIdx.y;
    const int base = b * NPT;
    const int tid = threadIdx.x;
    for (int j = tid; j < NPT; j += 256) { sp[j] = g_yp[base + j]; sg[j] = g_g[base + j]; }
    __syncthreads();
    const int warp = tid >> 5, lane = tid & 31;
    const int r0 = blockIdx.x * 32 + warp * 4;

    float qx[4], qy[4], qz[4], qn[4];
#pragma unroll
    for (int k = 0; k < 4; k++) {
        float4 q = g_xp[base + r0 + k];
        qx[k] = q.x; qy[k] = q.y; qz[k] = q.z; qn[k] = q.w;
    }
    float bv[4] = {INFINITY, INFINITY, INFINITY, INFINITY};
    int   bi[4] = {0, 0, 0, 0};
#pragma unroll 2
    for (int j = lane; j < NPT; j += 32) {
        const float4 p = sp[j];
        const float gg = sg[j];
#pragma unroll
        for (int k = 0; k < 4; k++) {
            float d = fmaf(qz[k], p.z, fmaf(qy[k], p.y, __fmul_rn(qx[k], p.x)));
            float s = fmaf(-2.f, d, __fadd_rn(qn[k], p.w));
            s = fmaxf(s, 0.f);
            float v = __fadd_rn(s, -gg);
            if (v < bv[k]) { bv[k] = v; bi[k] = j; }
        }
    }
#pragma unroll
    for (int k = 0; k < 4; k++) {
#pragma unroll
        for (int o = 16; o; o >>= 1) {
            float v2 = __shfl_xor_sync(0xffffffffu, bv[k], o);
            int   i2 = __shfl_xor_sync(0xffffffffu, bi[k], o);
            if (v2 < bv[k] || (v2 == bv[k] && i2 < bi[k])) { bv[k] = v2; bi[k] = i2; }
        }
    }
    if (lane == 0) {
#pragma unroll
        for (int k = 0; k < 4; k++) g_idx[base + r0 + k] = bi[k];
    }
}

// ---------------- gather + MLP head, write (v_pred, v) ----------------
__global__ void __launch_bounds__(256) k_mlp(const float* __restrict__ noise, const float* __restrict__ tt,
                                             const float* __restrict__ W1, const float* __restrict__ Wt,
                                             const float* __restrict__ b1, const float* __restrict__ W2,
                                             const float* __restrict__ b2, float* __restrict__ out) {
    __shared__ float sW1[3 * HID], sW2[HID * 3], sWt[HID], sb1[HID];
    const int tid = threadIdx.x;
    for (int i = tid; i < 3 * HID; i += 256) { sW1[i] = W1[i]; sW2[i] = W2[i]; }
    for (int i = tid; i < HID; i += 256) { sWt[i] = Wt[i]; sb1[i] = b1[i]; }
    __syncthreads();

    const int p = blockIdx.x * 256 + tid;
    const int b = p >> 11;
    const float t = tt[b];
    const int id = g_idx[p];
    const float4 y = g_yp[(b << 11) + id];
    const float n0 = noise[p * 3 + 0], n1 = noise[p * 3 + 1], n2 = noise[p * 3 + 2];
    const float v0 = __fadd_rn(n0, -y.x);
    const float v1 = __fadd_rn(n1, -y.y);
    const float v2 = __fadd_rn(n2, -y.z);
    const float omt = __fadd_rn(1.f, -t);
    const float x0t = __fadd_rn(__fmul_rn(omt, y.x), __fmul_rn(t, n0));
    const float x1t = __fadd_rn(__fmul_rn(omt, y.y), __fmul_rn(t, n1));
    const float x2t = __fadd_rn(__fmul_rn(omt, y.z), __fmul_rn(t, n2));

    float a0 = b2[0], a1 = b2[1], a2 = b2[2];
#pragma unroll 8
    for (int j = 0; j < HID; j++) {
        float h = fmaf(x2t, sW1[2 * HID + j], fmaf(x1t, sW1[HID + j], __fmul_rn(x0t, sW1[j])));
        h = __fadd_rn(__fadd_rn(h, __fmul_rn(t, sWt[j])), sb1[j]);
        h = fmaxf(h, 0.f);
        a0 = fmaf(h, sW2[j * 3 + 0], a0);
        a1 = fmaf(h, sW2[j * 3 + 1], a1);
        a2 = fmaf(h, sW2[j * 3 + 2], a2);
    }
    out[p * 3 + 0] = a0;
    out[p * 3 + 1] = a1;
    out[p * 3 + 2] = a2;
    out[NTOT * 3 + p * 3 + 0] = v0;
    out[NTOT * 3 + p * 3 + 1] = v1;
    out[NTOT * 3 + p * 3 + 2] = v2;
}

// ---------------- launcher ----------------
extern "C" void kernel_launch(void* const* d_in, const int* in_sizes, int n_in,
                              void* d_out, int out_size) {
    const float* cloud = (const float*)d_in[0];
    const float* noise = (const float*)d_in[1];
    const float* t     = (const float*)d_in[2];
    const float* W1    = (const float*)d_in[3];
    const float* Wt    = (const float*)d_in[4];
    const float* b1    = (const float*)d_in[5];
    const float* W2    = (const float*)d_in[6];
    const float* b2    = (const float*)d_in[7];
    float* out = (float*)d_out;

    k_std<<<BB, 256>>>(cloud);
    k_pack<<<NTOT / 256, 256>>>(cloud, noise);

    // EPS_LIST = np.geomspace(32.0, 0.001**2, 14).astype(np.float32)
    const double blur2 = 0.001 * 0.001;
    const double l0 = log10(32.0);
    const double l1 = log10(blur2);
    const double step = (l1 - l0) / (double)(NITER - 1);
    const double LOG2E = 1.4426950408889634;
    const dim3 grid(NPT / 32, BB);

    for (int it = 0; it < NITER; it++) {
        double ev;
        if (it == 0)              ev = 32.0;
        else if (it == NITER - 1) ev = blur2;
        else                      ev = pow(10.0, l0 + (double)it * step);
        const float eps = (float)ev;
        const float ie2 = (float)((double)(1.0f / eps) * LOG2E);
        k_half<0><<<grid, 256>>>(eps, ie2);  // f-update
        k_half<1><<<grid, 256>>>(eps, ie2);  // g-update
    }

    k_argmin<<<grid, 256>>>();
    k_mlp<<<NTOT / 256, 256>>>(noise, t, W1, Wt, b1, W2, b2, out);

    (void)in_sizes; (void)n_in; (void)out_size;
}